// round 2
// baseline (speedup 1.0000x reference)
#include <cuda_runtime.h>

typedef unsigned long long u64;

#define ND 20000
#define NG 20000
#define NC 10000
#define FD_K 2048
#define FG_K 1024
#define FC_K 512
#define DD 128
#define TT 10
#define BB 4096

// ---------------- scratch (device globals; no allocation allowed) -------------
__device__ float g_E_drug[ND * DD];
__device__ float g_E_gene[NG * DD];
__device__ float g_E_cell[NC * DD];
// XW[lt][b*10+s][384]
__device__ float g_XW[2 * 3 * BB * TT * 384];
// S[lt][b][128]
__device__ float g_S[2 * 3 * BB * DD];

// ---------------- f32x2 helpers ----------------
__device__ __forceinline__ u64 fma2(u64 a, u64 b, u64 c) {
    u64 d;
    asm("fma.rn.f32x2 %0, %1, %2, %3;" : "=l"(d) : "l"(a), "l"(b), "l"(c));
    return d;
}
__device__ __forceinline__ float2 unpack2(u64 a) {
    unsigned lo, hi;
    asm("mov.b64 {%0, %1}, %2;" : "=r"(lo), "=r"(hi) : "l"(a));
    return make_float2(__uint_as_float(lo), __uint_as_float(hi));
}
__device__ __forceinline__ float sigmf(float x) {
    return __fdividef(1.f, 1.f + __expf(-x));
}
__device__ __forceinline__ float tanh_fast(float x) {
    float ax = fabsf(x);
    float e = __expf(-2.f * ax);
    float r = __fdividef(1.f - e, 1.f + e);
    return copysignf(r, x);
}

// ---------------- 1) table projection: E = F @ W + b ----------------
// 256 threads = 64 col-pairs x 4 groups; 32 rows/block; K-tiles of 32.
__global__ __launch_bounds__(256) void proj_kernel(
    const float* __restrict__ F, const float* __restrict__ W,
    const float* __restrict__ bias, int sel, int N, int K)
{
    __shared__ float sW[32 * 128];
    __shared__ float2 sF2[32][34];   // duplicated splats, padded

    float* __restrict__ E = (sel == 0) ? g_E_drug : (sel == 1) ? g_E_gene : g_E_cell;

    int tid = threadIdx.x;
    int c   = tid & 63;      // float2 column 0..63
    int grp = tid >> 6;      // 0..3
    int row0 = blockIdx.x * 32;

    u64 acc[8];
#pragma unroll
    for (int i = 0; i < 8; i++) acc[i] = 0ull;

    for (int k0 = 0; k0 < K; k0 += 32) {
        // stage W tile 32x128 (coalesced float4)
        const float4* wsrc = (const float4*)(W + (size_t)k0 * 128);
        float4* wdst = (float4*)sW;
#pragma unroll
        for (int i = 0; i < 4; i++) wdst[tid + i * 256] = wsrc[tid + i * 256];
        // stage F tile 32 rows x 32 k, duplicated for splat FMA2
        {
            int r  = tid >> 3;
            int kq = (tid & 7) * 4;
            int row = row0 + r;
            int rr = row < N ? row : N - 1;
            float4 f = *(const float4*)(F + (size_t)rr * K + k0 + kq);
            sF2[r][kq + 0] = make_float2(f.x, f.x);
            sF2[r][kq + 1] = make_float2(f.y, f.y);
            sF2[r][kq + 2] = make_float2(f.z, f.z);
            sF2[r][kq + 3] = make_float2(f.w, f.w);
        }
        __syncthreads();
#pragma unroll
        for (int kk = 0; kk < 32; ++kk) {
            u64 w = *(const u64*)(sW + kk * 128 + 2 * c);
#pragma unroll
            for (int i = 0; i < 8; i++) {
                u64 x = *(const u64*)(&sF2[grp * 8 + i][kk]);
                acc[i] = fma2(x, w, acc[i]);
            }
        }
        __syncthreads();
    }
    float2 b2 = ((const float2*)bias)[c];
#pragma unroll
    for (int i = 0; i < 8; i++) {
        int row = row0 + grp * 8 + i;
        if (row < N) {
            float2 a = unpack2(acc[i]);
            a.x += b2.x; a.y += b2.y;
            ((float2*)E)[(size_t)row * 64 + c] = a;
        }
    }
}

// ---------------- 2) XW precompute: XW[lt][row][384] = x_row @ W_lt + b_lt ----
// grid: x = 40960/32, y = 6. blockDim 384 = 192 cols x 2 groups, 16 rows/thread.
__global__ __launch_bounds__(384) void xw_kernel(
    const float* __restrict__ gruW, const float* __restrict__ gruB,
    const int* __restrict__ nbr_d, const int* __restrict__ nbr_g,
    const int* __restrict__ nbr_c)
{
    extern __shared__ float sm[];
    float*  sW  = sm;                          // 128*384 floats
    float2* sX2 = (float2*)(sm + 128 * 384);   // [32][128] duplicated splats
    int*    sId = (int*)(sX2 + 32 * 128);      // [32]

    int tid = threadIdx.x;
    int lt = blockIdx.y;
    int t = lt % 3;
    const int* nbr = (t == 0) ? nbr_d : (t == 1) ? nbr_g : nbr_c;
    const float* Etab = (t == 0) ? g_E_drug : (t == 1) ? g_E_gene : g_E_cell;
    int grow0 = blockIdx.x * 32;

    if (tid < 32) sId[tid] = nbr[grow0 + tid];   // grow = b*10+s matches [B][T]
    {
        const float4* src = (const float4*)(gruW + (size_t)lt * 49152);
        float4* dst = (float4*)sW;
#pragma unroll
        for (int i = 0; i < 32; i++) dst[tid + i * 384] = src[tid + i * 384];
    }
    __syncthreads();
    for (int idx = tid; idx < 32 * 128; idx += 384) {
        int rr = idx >> 7, kk = idx & 127;
        int id = sId[rr];
        float v = (id >= 0) ? Etab[(size_t)id * 128 + kk] : 0.f;
        sX2[rr * 128 + kk] = make_float2(v, v);
    }
    __syncthreads();

    int c = tid % 192, grp = tid / 192;
    u64 acc[16];
#pragma unroll
    for (int i = 0; i < 16; i++) acc[i] = 0ull;

#pragma unroll 4
    for (int k = 0; k < 128; k++) {
        u64 w = *(const u64*)(sW + k * 384 + 2 * c);
#pragma unroll
        for (int i = 0; i < 16; i++)
            acc[i] = fma2(*(const u64*)(sX2 + (grp * 16 + i) * 128 + k), w, acc[i]);
    }
    float2 b2 = ((const float2*)(gruB + lt * 384))[c];
#pragma unroll
    for (int i = 0; i < 16; i++) {
        int grow = grow0 + grp * 16 + i;
        float2 a = unpack2(acc[i]);
        a.x += b2.x; a.y += b2.y;
        ((float2*)g_XW)[((size_t)lt * 40960 + grow) * 192 + c] = a;
    }
}

// ---------------- 3) GRU recurrence + masked mean ----------------
// grid: x = 4096/32, y = 6. blockDim 256 = 64 dim-pairs x 4 row-parts (8 rows each).
// U (192KB) + duplicated H (32KB) resident in smem.
__global__ __launch_bounds__(256) void gru_kernel(
    const float* __restrict__ gruU,
    const int* __restrict__ nbr_d, const int* __restrict__ nbr_g,
    const int* __restrict__ nbr_c)
{
    extern __shared__ float sm[];
    float*  sU  = sm;                          // 128*384
    float2* sH2 = (float2*)(sm + 49152);       // [32][128] duplicated splats
    float*  sM  = (float*)(sH2 + 32 * 128);    // [32][10]
    float*  sCnt = sM + 320;                   // [32]

    int tid = threadIdx.x;
    int lt = blockIdx.y;
    int t = lt % 3;
    const int* nbr = (t == 0) ? nbr_d : (t == 1) ? nbr_g : nbr_c;
    int b0 = blockIdx.x * 32;

    {
        const float4* src = (const float4*)(gruU + (size_t)lt * 49152);
        float4* dst = (float4*)sU;
#pragma unroll
        for (int i = 0; i < 48; i++) dst[tid + i * 256] = src[tid + i * 256];
    }
    // FIX (R1): strided loop — blockDim is 256, sM has 320 entries
    for (int i = tid; i < 320; i += 256) {
        int rr = i / 10, s = i % 10;
        sM[i] = (nbr[(size_t)(b0 + rr) * 10 + s] >= 0) ? 1.f : 0.f;
    }
    for (int i = tid; i < 4096; i += 256) sH2[i] = make_float2(0.f, 0.f);
    __syncthreads();
    if (tid < 32) {
        float cnt = 0.f;
        for (int s = 0; s < 10; s++) cnt += sM[tid * 10 + s];
        sCnt[tid] = fmaxf(cnt, 1.f);
    }
    __syncthreads();

    int d2 = tid & 63, rpart = tid >> 6;
    float2 msum[8];
#pragma unroll
    for (int i = 0; i < 8; i++) msum[i] = make_float2(0.f, 0.f);

    for (int s = 0; s < 10; s++) {
        u64 az[8], ar[8], an[8];
#pragma unroll
        for (int i = 0; i < 8; i++) { az[i] = 0ull; ar[i] = 0ull; an[i] = 0ull; }

#pragma unroll 2
        for (int k = 0; k < 128; k++) {
            u64 uz = *(const u64*)(sU + k * 384 + 2 * d2);
            u64 ur = *(const u64*)(sU + k * 384 + 128 + 2 * d2);
            u64 un = *(const u64*)(sU + k * 384 + 256 + 2 * d2);
#pragma unroll
            for (int i = 0; i < 8; i++) {
                u64 hh = *(const u64*)(sH2 + (rpart * 8 + i) * 128 + k);
                az[i] = fma2(hh, uz, az[i]);
                ar[i] = fma2(hh, ur, ar[i]);
                an[i] = fma2(hh, un, an[i]);
            }
        }
        __syncthreads();   // all reads of H done before updates
#pragma unroll
        for (int i = 0; i < 8; i++) {
            int rl = rpart * 8 + i;
            int bg = b0 + rl;
            const float* xwb = g_XW + ((size_t)lt * 40960 + (size_t)bg * 10 + s) * 384;
            float2 xz = *(const float2*)(xwb + 2 * d2);
            float2 xr = *(const float2*)(xwb + 128 + 2 * d2);
            float2 xn = *(const float2*)(xwb + 256 + 2 * d2);
            float2 hz = unpack2(az[i]), hr = unpack2(ar[i]), hn = unpack2(an[i]);
            float hox = sH2[rl * 128 + 2 * d2].x;
            float hoy = sH2[rl * 128 + 2 * d2 + 1].x;
            float zx = sigmf(xz.x + hz.x), zy = sigmf(xz.y + hz.y);
            float rx = sigmf(xr.x + hr.x), ry = sigmf(xr.y + hr.y);
            float nx = tanh_fast(xn.x + rx * hn.x);
            float ny = tanh_fast(xn.y + ry * hn.y);
            float hx = (1.f - zx) * nx + zx * hox;
            float hy = (1.f - zy) * ny + zy * hoy;
            sH2[rl * 128 + 2 * d2]     = make_float2(hx, hx);
            sH2[rl * 128 + 2 * d2 + 1] = make_float2(hy, hy);
            float m = sM[rl * 10 + s];
            msum[i].x += m * hx;
            msum[i].y += m * hy;
        }
        __syncthreads();
    }
#pragma unroll
    for (int i = 0; i < 8; i++) {
        int rl = rpart * 8 + i;
        int bg = b0 + rl;
        float invc = 1.f / sCnt[rl];
        ((float2*)g_S)[((size_t)lt * BB + bg) * 64 + d2] =
            make_float2(msum[i].x * invc, msum[i].y * invc);
    }
}

// ---------------- 4) attention combine (2 layers) ----------------
__device__ __forceinline__ float blkred(float v, float* red) {
    int d = threadIdx.x;
    red[d] = v;
    __syncthreads();
#pragma unroll
    for (int st = 64; st > 0; st >>= 1) {
        if (d < st) red[d] += red[d + st];
        __syncthreads();
    }
    float r = red[0];
    __syncthreads();
    return r;
}

__global__ __launch_bounds__(128) void final_kernel(
    const float* __restrict__ att, const int* __restrict__ ids,
    float* __restrict__ out)
{
    __shared__ float red[128];
    __shared__ float sC[3][128];
    int b = blockIdx.x, d = threadIdx.x;
    float h = g_E_drug[(size_t)ids[b] * 128 + d];
#pragma unroll
    for (int l = 0; l < 2; l++) {
        for (int t = 0; t < 3; t++)
            sC[t][d] = g_S[((size_t)(l * 3 + t) * BB + b) * 128 + d];
        __syncthreads();
        float a1 = att[l * 256 + d], a2 = att[l * 256 + 128 + d];
        float dh1 = blkred(h * a1, red);
        float dh2 = blkred(h * a2, red);
        float e0 = dh1 + dh2;
        float e1 = dh1 + blkred(sC[0][d] * a2, red);
        float e2 = dh1 + blkred(sC[1][d] * a2, red);
        float e3 = dh1 + blkred(sC[2][d] * a2, red);
        e0 = e0 > 0.f ? e0 : 0.01f * e0;
        e1 = e1 > 0.f ? e1 : 0.01f * e1;
        e2 = e2 > 0.f ? e2 : 0.01f * e2;
        e3 = e3 > 0.f ? e3 : 0.01f * e3;
        float mx = fmaxf(fmaxf(e0, e1), fmaxf(e2, e3));
        float w0 = __expf(e0 - mx), w1 = __expf(e1 - mx);
        float w2 = __expf(e2 - mx), w3 = __expf(e3 - mx);
        float inv = __fdividef(1.f, w0 + w1 + w2 + w3);
        h = (w0 * h + w1 * sC[0][d] + w2 * sC[1][d] + w3 * sC[2][d]) * inv;
        __syncthreads();
    }
    out[(size_t)b * 128 + d] = h;
}

// ---------------- launch ----------------
extern "C" void kernel_launch(void* const* d_in, const int* in_sizes, int n_in,
                              void* d_out, int out_size)
{
    const float* drug = (const float*)d_in[0];
    const float* gene = (const float*)d_in[1];
    const float* cell = (const float*)d_in[2];
    const float* Wd = (const float*)d_in[3];
    const float* bd = (const float*)d_in[4];
    const float* Wg = (const float*)d_in[5];
    const float* bg = (const float*)d_in[6];
    const float* Wc = (const float*)d_in[7];
    const float* bc = (const float*)d_in[8];
    const float* gW = (const float*)d_in[9];
    const float* gU = (const float*)d_in[10];
    const float* gb = (const float*)d_in[11];
    const float* att = (const float*)d_in[12];
    const int* ids = (const int*)d_in[13];
    const int* nd = (const int*)d_in[14];
    const int* ng = (const int*)d_in[15];
    const int* nc = (const int*)d_in[16];
    float* out = (float*)d_out;

    const int XW_SMEM  = 128 * 384 * 4 + 32 * 128 * 8 + 32 * 4;          // 229504
    const int GRU_SMEM = 128 * 384 * 4 + 32 * 128 * 8 + 320 * 4 + 32 * 4; // 230784
    cudaFuncSetAttribute(xw_kernel, cudaFuncAttributeMaxDynamicSharedMemorySize, XW_SMEM);
    cudaFuncSetAttribute(gru_kernel, cudaFuncAttributeMaxDynamicSharedMemorySize, GRU_SMEM);

    // 1) project tables once
    proj_kernel<<<(ND + 31) / 32, 256>>>(drug, Wd, bd, 0, ND, FD_K);
    proj_kernel<<<(NG + 31) / 32, 256>>>(gene, Wg, bg, 1, NG, FG_K);
    proj_kernel<<<(NC + 31) / 32, 256>>>(cell, Wc, bc, 2, NC, FC_K);

    // 2) XW = gathered X @ W + b for all 6 (layer,type)
    xw_kernel<<<dim3(40960 / 32, 6), 384, XW_SMEM>>>(gW, gb, nd, ng, nc);

    // 3) GRU recurrence + masked mean for all 6 (layer,type)
    gru_kernel<<<dim3(BB / 32, 6), 256, GRU_SMEM>>>(gU, nd, ng, nc);

    // 4) attention combine (both layers) + output
    final_kernel<<<BB, 128>>>(att, ids, out);
}

// round 3
// speedup vs baseline: 1.0960x; 1.0960x over previous
#include <cuda_runtime.h>

typedef unsigned long long u64;

#define ND 20000
#define NG 20000
#define NC 10000
#define DD 128
#define TT 10
#define BB 4096

// ---------------- scratch (device globals; no allocation allowed) -------------
__device__ float g_E_drug[ND * DD];
__device__ float g_E_gene[NG * DD];
__device__ float g_E_cell[NC * DD];
// XW[lt][b*10+s][384]
__device__ float g_XW[2 * 3 * BB * TT * 384];
// S[lt][b][128]
__device__ float g_S[2 * 3 * BB * DD];

// ---------------- f32x2 helpers ----------------
__device__ __forceinline__ u64 fma2(u64 a, u64 b, u64 c) {
    u64 d;
    asm("fma.rn.f32x2 %0, %1, %2, %3;" : "=l"(d) : "l"(a), "l"(b), "l"(c));
    return d;
}
__device__ __forceinline__ float2 unpack2(u64 a) {
    unsigned lo, hi;
    asm("mov.b64 {%0, %1}, %2;" : "=r"(lo), "=r"(hi) : "l"(a));
    return make_float2(__uint_as_float(lo), __uint_as_float(hi));
}
__device__ __forceinline__ u64 splat2(float v) {
    u64 d;
    unsigned u = __float_as_uint(v);
    asm("mov.b64 %0, {%1, %1};" : "=l"(d) : "r"(u));
    return d;
}
__device__ __forceinline__ float sigmf(float x) {
    return __fdividef(1.f, 1.f + __expf(-x));
}
__device__ __forceinline__ float tanh_fast(float x) {
    float ax = fabsf(x);
    float e = __expf(-2.f * ax);
    float r = __fdividef(1.f - e, 1.f + e);
    return copysignf(r, x);
}

// ---------------- 1) table projection: E = F @ W + b ----------------
// 256 threads; 128 rows/block; thread tile = 8 rows x 4 col-pairs.
// K-tiles of 32, register-prefetch pipeline over tiles.
__global__ __launch_bounds__(256) void proj_kernel(
    const float* __restrict__ F, const float* __restrict__ W,
    const float* __restrict__ bias, int sel, int N, int K)
{
    __shared__ float sW[32 * 128];     // 16KB
    __shared__ u64 sF2[128 * 33];      // 33KB, pitch 33 u64

    float* __restrict__ E = (sel == 0) ? g_E_drug : (sel == 1) ? g_E_gene : g_E_cell;

    int tid = threadIdx.x;
    int cg = tid & 15;       // colgroup: pairs cg*4 .. cg*4+3
    int rg = tid >> 4;       // rowgroup: rows rg*8 .. rg*8+7
    int row0 = blockIdx.x * 128;

    // staging coords
    int sr  = tid >> 1;            // staged row 0..127
    int skq = (tid & 1) * 16;      // staged k offset 0 or 16

    u64 acc[8][4];
#pragma unroll
    for (int i = 0; i < 8; i++)
#pragma unroll
        for (int j = 0; j < 4; j++) acc[i][j] = 0ull;

    int srow = row0 + sr;
    int srr = srow < N ? srow : N - 1;
    const float* frow = F + (size_t)srr * K;

    // preload tile 0 into registers
    float4 wreg[4], freg[4];
    {
        const float4* wsrc = (const float4*)W;
#pragma unroll
        for (int i = 0; i < 4; i++) wreg[i] = wsrc[tid + i * 256];
        const float4* fsrc = (const float4*)(frow + skq);
#pragma unroll
        for (int i = 0; i < 4; i++) freg[i] = fsrc[i];
    }

    for (int k0 = 0; k0 < K; k0 += 32) {
        __syncthreads();  // previous tile's reads done
        // commit registers to smem
#pragma unroll
        for (int i = 0; i < 4; i++) ((float4*)sW)[tid + i * 256] = wreg[i];
#pragma unroll
        for (int i = 0; i < 4; i++) {
            int base = sr * 33 + skq + i * 4;
            sF2[base + 0] = splat2(freg[i].x);
            sF2[base + 1] = splat2(freg[i].y);
            sF2[base + 2] = splat2(freg[i].z);
            sF2[base + 3] = splat2(freg[i].w);
        }
        __syncthreads();
        // prefetch next tile
        if (k0 + 32 < K) {
            const float4* wsrc = (const float4*)(W + (size_t)(k0 + 32) * 128);
#pragma unroll
            for (int i = 0; i < 4; i++) wreg[i] = wsrc[tid + i * 256];
            const float4* fsrc = (const float4*)(frow + k0 + 32 + skq);
#pragma unroll
            for (int i = 0; i < 4; i++) freg[i] = fsrc[i];
        }
        // compute
#pragma unroll 4
        for (int kk = 0; kk < 32; kk++) {
            u64 w[4];
#pragma unroll
            for (int j = 0; j < 4; j++)
                w[j] = *(const u64*)(sW + kk * 128 + 8 * cg + 2 * j);
            u64 x[8];
#pragma unroll
            for (int i = 0; i < 8; i++)
                x[i] = sF2[(rg * 8 + i) * 33 + kk];
#pragma unroll
            for (int i = 0; i < 8; i++)
#pragma unroll
                for (int j = 0; j < 4; j++)
                    acc[i][j] = fma2(x[i], w[j], acc[i][j]);
        }
    }

    float2 b2[4];
#pragma unroll
    for (int j = 0; j < 4; j++) b2[j] = ((const float2*)bias)[cg * 4 + j];
#pragma unroll
    for (int i = 0; i < 8; i++) {
        int row = row0 + rg * 8 + i;
        if (row < N) {
#pragma unroll
            for (int j = 0; j < 4; j++) {
                float2 a = unpack2(acc[i][j]);
                a.x += b2[j].x; a.y += b2[j].y;
                ((float2*)E)[(size_t)row * 64 + cg * 4 + j] = a;
            }
        }
    }
}

// ---------------- 2) XW precompute: XW[lt][row][384] = x_row @ W_lt + b_lt ----
// 256 threads; 64 gathered rows/block; thread tile = 8 rows x 6 col-pairs
// (pairs cg + j*32). W streamed as two 64-k smem tiles.
__global__ __launch_bounds__(256) void xw_kernel(
    const float* __restrict__ gruW, const float* __restrict__ gruB,
    const int* __restrict__ nbr_d, const int* __restrict__ nbr_g,
    const int* __restrict__ nbr_c)
{
    extern __shared__ float sm[];
    float* sW = sm;                        // 64*384 floats = 96KB (k-tile)
    u64*   sX2 = (u64*)(sm + 24576);       // 64 rows x 128 = 64KB
    int*   sId = (int*)(sX2 + 64 * 128);   // 64

    int tid = threadIdx.x;
    int lt = blockIdx.y;
    int t = lt % 3;
    const int* nbr = (t == 0) ? nbr_d : (t == 1) ? nbr_g : nbr_c;
    const float* Etab = (t == 0) ? g_E_drug : (t == 1) ? g_E_gene : g_E_cell;
    int grow0 = blockIdx.x * 64;

    if (tid < 64) sId[tid] = nbr[grow0 + tid];
    __syncthreads();

    // stage gathered X (duplicated splats), all 128 k
    {
        int r = tid >> 2;
        int kq = (tid & 3) * 32;
        int id = sId[r];
        const float4* src = (id >= 0) ? (const float4*)(Etab + (size_t)id * 128 + kq) : 0;
#pragma unroll
        for (int i = 0; i < 8; i++) {
            float4 f = (id >= 0) ? src[i] : make_float4(0.f, 0.f, 0.f, 0.f);
            int base = r * 128 + kq + i * 4;
            sX2[base + 0] = splat2(f.x);
            sX2[base + 1] = splat2(f.y);
            sX2[base + 2] = splat2(f.z);
            sX2[base + 3] = splat2(f.w);
        }
    }

    int cg = tid & 31;       // pairs cg + j*32, j in [0,6)
    int rg = tid >> 5;       // rows rg*8 .. rg*8+7

    u64 acc[8][6];
#pragma unroll
    for (int i = 0; i < 8; i++)
#pragma unroll
        for (int j = 0; j < 6; j++) acc[i][j] = 0ull;

#pragma unroll
    for (int tile = 0; tile < 2; tile++) {
        __syncthreads();
        const float4* wsrc = (const float4*)(gruW + (size_t)lt * 49152 + tile * 64 * 384);
#pragma unroll
        for (int i = 0; i < 24; i++) ((float4*)sW)[tid + i * 256] = wsrc[tid + i * 256];
        __syncthreads();
#pragma unroll 4
        for (int kk = 0; kk < 64; kk++) {
            u64 x[8];
#pragma unroll
            for (int i = 0; i < 8; i++)
                x[i] = sX2[(rg * 8 + i) * 128 + tile * 64 + kk];
            u64 w[6];
#pragma unroll
            for (int j = 0; j < 6; j++)
                w[j] = *(const u64*)(sW + kk * 384 + 2 * (cg + j * 32));
#pragma unroll
            for (int i = 0; i < 8; i++)
#pragma unroll
                for (int j = 0; j < 6; j++)
                    acc[i][j] = fma2(x[i], w[j], acc[i][j]);
        }
    }

    float2 b2[6];
#pragma unroll
    for (int j = 0; j < 6; j++) b2[j] = ((const float2*)(gruB + lt * 384))[cg + j * 32];
#pragma unroll
    for (int i = 0; i < 8; i++) {
        int grow = grow0 + rg * 8 + i;
#pragma unroll
        for (int j = 0; j < 6; j++) {
            float2 a = unpack2(acc[i][j]);
            a.x += b2[j].x; a.y += b2[j].y;
            ((float2*)g_XW)[((size_t)lt * 40960 + grow) * 192 + cg + j * 32] = a;
        }
    }
}

// ---------------- 3) GRU recurrence + masked mean ----------------
// grid: x = 4096/32, y = 6. blockDim 256 = 64 dim-pairs x 4 row-parts (8 rows each).
// U (192KB) + duplicated H (32KB) resident in smem. (fma/MUFU-bound; unchanged)
__global__ __launch_bounds__(256) void gru_kernel(
    const float* __restrict__ gruU,
    const int* __restrict__ nbr_d, const int* __restrict__ nbr_g,
    const int* __restrict__ nbr_c)
{
    extern __shared__ float sm[];
    float*  sU  = sm;                          // 128*384
    float2* sH2 = (float2*)(sm + 49152);       // [32][128] duplicated splats
    float*  sM  = (float*)(sH2 + 32 * 128);    // [32][10]
    float*  sCnt = sM + 320;                   // [32]

    int tid = threadIdx.x;
    int lt = blockIdx.y;
    int t = lt % 3;
    const int* nbr = (t == 0) ? nbr_d : (t == 1) ? nbr_g : nbr_c;
    int b0 = blockIdx.x * 32;

    {
        const float4* src = (const float4*)(gruU + (size_t)lt * 49152);
        float4* dst = (float4*)sU;
#pragma unroll
        for (int i = 0; i < 48; i++) dst[tid + i * 256] = src[tid + i * 256];
    }
    for (int i = tid; i < 320; i += 256) {
        int rr = i / 10, s = i % 10;
        sM[i] = (nbr[(size_t)(b0 + rr) * 10 + s] >= 0) ? 1.f : 0.f;
    }
    for (int i = tid; i < 4096; i += 256) sH2[i] = make_float2(0.f, 0.f);
    __syncthreads();
    if (tid < 32) {
        float cnt = 0.f;
        for (int s = 0; s < 10; s++) cnt += sM[tid * 10 + s];
        sCnt[tid] = fmaxf(cnt, 1.f);
    }
    __syncthreads();

    int d2 = tid & 63, rpart = tid >> 6;
    float2 msum[8];
#pragma unroll
    for (int i = 0; i < 8; i++) msum[i] = make_float2(0.f, 0.f);

    for (int s = 0; s < 10; s++) {
        u64 az[8], ar[8], an[8];
#pragma unroll
        for (int i = 0; i < 8; i++) { az[i] = 0ull; ar[i] = 0ull; an[i] = 0ull; }

#pragma unroll 2
        for (int k = 0; k < 128; k++) {
            u64 uz = *(const u64*)(sU + k * 384 + 2 * d2);
            u64 ur = *(const u64*)(sU + k * 384 + 128 + 2 * d2);
            u64 un = *(const u64*)(sU + k * 384 + 256 + 2 * d2);
#pragma unroll
            for (int i = 0; i < 8; i++) {
                u64 hh = *(const u64*)(sH2 + (rpart * 8 + i) * 128 + k);
                az[i] = fma2(hh, uz, az[i]);
                ar[i] = fma2(hh, ur, ar[i]);
                an[i] = fma2(hh, un, an[i]);
            }
        }
        __syncthreads();   // all reads of H done before updates
#pragma unroll
        for (int i = 0; i < 8; i++) {
            int rl = rpart * 8 + i;
            int bg = b0 + rl;
            const float* xwb = g_XW + ((size_t)lt * 40960 + (size_t)bg * 10 + s) * 384;
            float2 xz = *(const float2*)(xwb + 2 * d2);
            float2 xr = *(const float2*)(xwb + 128 + 2 * d2);
            float2 xn = *(const float2*)(xwb + 256 + 2 * d2);
            float2 hz = unpack2(az[i]), hr = unpack2(ar[i]), hn = unpack2(an[i]);
            float hox = sH2[rl * 128 + 2 * d2].x;
            float hoy = sH2[rl * 128 + 2 * d2 + 1].x;
            float zx = sigmf(xz.x + hz.x), zy = sigmf(xz.y + hz.y);
            float rx = sigmf(xr.x + hr.x), ry = sigmf(xr.y + hr.y);
            float nx = tanh_fast(xn.x + rx * hn.x);
            float ny = tanh_fast(xn.y + ry * hn.y);
            float hx = (1.f - zx) * nx + zx * hox;
            float hy = (1.f - zy) * ny + zy * hoy;
            sH2[rl * 128 + 2 * d2]     = make_float2(hx, hx);
            sH2[rl * 128 + 2 * d2 + 1] = make_float2(hy, hy);
            float m = sM[rl * 10 + s];
            msum[i].x += m * hx;
            msum[i].y += m * hy;
        }
        __syncthreads();
    }
#pragma unroll
    for (int i = 0; i < 8; i++) {
        int rl = rpart * 8 + i;
        int bg = b0 + rl;
        float invc = 1.f / sCnt[rl];
        ((float2*)g_S)[((size_t)lt * BB + bg) * 64 + d2] =
            make_float2(msum[i].x * invc, msum[i].y * invc);
    }
}

// ---------------- 4) attention combine (2 layers) ----------------
__device__ __forceinline__ float blkred(float v, float* red) {
    int d = threadIdx.x;
    red[d] = v;
    __syncthreads();
#pragma unroll
    for (int st = 64; st > 0; st >>= 1) {
        if (d < st) red[d] += red[d + st];
        __syncthreads();
    }
    float r = red[0];
    __syncthreads();
    return r;
}

__global__ __launch_bounds__(128) void final_kernel(
    const float* __restrict__ att, const int* __restrict__ ids,
    float* __restrict__ out)
{
    __shared__ float red[128];
    __shared__ float sC[3][128];
    int b = blockIdx.x, d = threadIdx.x;
    float h = g_E_drug[(size_t)ids[b] * 128 + d];
#pragma unroll
    for (int l = 0; l < 2; l++) {
        for (int t = 0; t < 3; t++)
            sC[t][d] = g_S[((size_t)(l * 3 + t) * BB + b) * 128 + d];
        __syncthreads();
        float a1 = att[l * 256 + d], a2 = att[l * 256 + 128 + d];
        float dh1 = blkred(h * a1, red);
        float dh2 = blkred(h * a2, red);
        float e0 = dh1 + dh2;
        float e1 = dh1 + blkred(sC[0][d] * a2, red);
        float e2 = dh1 + blkred(sC[1][d] * a2, red);
        float e3 = dh1 + blkred(sC[2][d] * a2, red);
        e0 = e0 > 0.f ? e0 : 0.01f * e0;
        e1 = e1 > 0.f ? e1 : 0.01f * e1;
        e2 = e2 > 0.f ? e2 : 0.01f * e2;
        e3 = e3 > 0.f ? e3 : 0.01f * e3;
        float mx = fmaxf(fmaxf(e0, e1), fmaxf(e2, e3));
        float w0 = __expf(e0 - mx), w1 = __expf(e1 - mx);
        float w2 = __expf(e2 - mx), w3 = __expf(e3 - mx);
        float inv = __fdividef(1.f, w0 + w1 + w2 + w3);
        h = (w0 * h + w1 * sC[0][d] + w2 * sC[1][d] + w3 * sC[2][d]) * inv;
        __syncthreads();
    }
    out[(size_t)b * 128 + d] = h;
}

// ---------------- launch ----------------
extern "C" void kernel_launch(void* const* d_in, const int* in_sizes, int n_in,
                              void* d_out, int out_size)
{
    const float* drug = (const float*)d_in[0];
    const float* gene = (const float*)d_in[1];
    const float* cell = (const float*)d_in[2];
    const float* Wd = (const float*)d_in[3];
    const float* bd = (const float*)d_in[4];
    const float* Wg = (const float*)d_in[5];
    const float* bg = (const float*)d_in[6];
    const float* Wc = (const float*)d_in[7];
    const float* bc = (const float*)d_in[8];
    const float* gW = (const float*)d_in[9];
    const float* gU = (const float*)d_in[10];
    const float* gb = (const float*)d_in[11];
    const float* att = (const float*)d_in[12];
    const int* ids = (const int*)d_in[13];
    const int* nd = (const int*)d_in[14];
    const int* ng = (const int*)d_in[15];
    const int* nc = (const int*)d_in[16];
    float* out = (float*)d_out;

    const int XW_SMEM  = 64 * 384 * 4 + 64 * 128 * 8 + 64 * 4;            // 164_352
    const int GRU_SMEM = 128 * 384 * 4 + 32 * 128 * 8 + 320 * 4 + 32 * 4; // 230784
    cudaFuncSetAttribute(xw_kernel, cudaFuncAttributeMaxDynamicSharedMemorySize, XW_SMEM);
    cudaFuncSetAttribute(gru_kernel, cudaFuncAttributeMaxDynamicSharedMemorySize, GRU_SMEM);

    // 1) project tables once
    proj_kernel<<<(ND + 127) / 128, 256>>>(drug, Wd, bd, 0, ND, 2048);
    proj_kernel<<<(NG + 127) / 128, 256>>>(gene, Wg, bg, 1, NG, 1024);
    proj_kernel<<<(NC + 127) / 128, 256>>>(cell, Wc, bc, 2, NC, 512);

    // 2) XW = gathered X @ W + b for all 6 (layer,type)
    xw_kernel<<<dim3(40960 / 64, 6), 256, XW_SMEM>>>(gW, gb, nd, ng, nc);

    // 3) GRU recurrence + masked mean for all 6 (layer,type)
    gru_kernel<<<dim3(BB / 32, 6), 256, GRU_SMEM>>>(gU, nd, ng, nc);

    // 4) attention combine (both layers) + output
    final_kernel<<<BB, 128>>>(att, ids, out);
}

// round 4
// speedup vs baseline: 1.1229x; 1.0245x over previous
#include <cuda_runtime.h>

typedef unsigned long long u64;

#define ND 20000
#define NG 20000
#define NC 10000
#define DD 128
#define TT 10
#define BB 4096

// ---------------- scratch (device globals; no allocation allowed) -------------
__device__ float g_E_drug[ND * DD];
__device__ float g_E_gene[NG * DD];
__device__ float g_E_cell[NC * DD];
// XW[lt][b*10+s][384]
__device__ float g_XW[2 * 3 * BB * TT * 384];
// S[lt][b][128]
__device__ float g_S[2 * 3 * BB * DD];

// ---------------- helpers ----------------
__device__ __forceinline__ u64 fma2(u64 a, u64 b, u64 c) {
    u64 d;
    asm("fma.rn.f32x2 %0, %1, %2, %3;" : "=l"(d) : "l"(a), "l"(b), "l"(c));
    return d;
}
__device__ __forceinline__ float2 unpack2(u64 a) {
    unsigned lo, hi;
    asm("mov.b64 {%0, %1}, %2;" : "=r"(lo), "=r"(hi) : "l"(a));
    return make_float2(__uint_as_float(lo), __uint_as_float(hi));
}
__device__ __forceinline__ u64 splat2(float v) {
    u64 d;
    unsigned u = __float_as_uint(v);
    asm("mov.b64 %0, {%1, %1};" : "=l"(d) : "r"(u));
    return d;
}
__device__ __forceinline__ unsigned smem_addr(const void* p) {
    return (unsigned)__cvta_generic_to_shared(p);
}
__device__ __forceinline__ void cp16(unsigned dst, const void* src) {
    asm volatile("cp.async.cg.shared.global [%0], [%1], 16;" :: "r"(dst), "l"(src));
}
__device__ __forceinline__ float sigmf(float x) {
    return __fdividef(1.f, 1.f + __expf(-x));
}
__device__ __forceinline__ float tanh_fast(float x) {
    float ax = fabsf(x);
    float e = __expf(-2.f * ax);
    float r = __fdividef(1.f - e, 1.f + e);
    return copysignf(r, x);
}

// ---------------- 1) table projection: E = F @ W + b ----------------
// 256 threads; 128 rows/block; thread tile = 8 rows x 4 col-pairs.
__global__ __launch_bounds__(256) void proj_kernel(
    const float* __restrict__ F, const float* __restrict__ W,
    const float* __restrict__ bias, int sel, int N, int K)
{
    __shared__ float sW[32 * 128];
    __shared__ u64 sF2[128 * 33];

    float* __restrict__ E = (sel == 0) ? g_E_drug : (sel == 1) ? g_E_gene : g_E_cell;

    int tid = threadIdx.x;
    int cg = tid & 15;
    int rg = tid >> 4;
    int row0 = blockIdx.x * 128;
    int sr  = tid >> 1;
    int skq = (tid & 1) * 16;

    u64 acc[8][4];
#pragma unroll
    for (int i = 0; i < 8; i++)
#pragma unroll
        for (int j = 0; j < 4; j++) acc[i][j] = 0ull;

    int srow = row0 + sr;
    int srr = srow < N ? srow : N - 1;
    const float* frow = F + (size_t)srr * K;

    float4 wreg[4], freg[4];
    {
        const float4* wsrc = (const float4*)W;
#pragma unroll
        for (int i = 0; i < 4; i++) wreg[i] = wsrc[tid + i * 256];
        const float4* fsrc = (const float4*)(frow + skq);
#pragma unroll
        for (int i = 0; i < 4; i++) freg[i] = fsrc[i];
    }

    for (int k0 = 0; k0 < K; k0 += 32) {
        __syncthreads();
#pragma unroll
        for (int i = 0; i < 4; i++) ((float4*)sW)[tid + i * 256] = wreg[i];
#pragma unroll
        for (int i = 0; i < 4; i++) {
            int base = sr * 33 + skq + i * 4;
            sF2[base + 0] = splat2(freg[i].x);
            sF2[base + 1] = splat2(freg[i].y);
            sF2[base + 2] = splat2(freg[i].z);
            sF2[base + 3] = splat2(freg[i].w);
        }
        __syncthreads();
        if (k0 + 32 < K) {
            const float4* wsrc = (const float4*)(W + (size_t)(k0 + 32) * 128);
#pragma unroll
            for (int i = 0; i < 4; i++) wreg[i] = wsrc[tid + i * 256];
            const float4* fsrc = (const float4*)(frow + k0 + 32 + skq);
#pragma unroll
            for (int i = 0; i < 4; i++) freg[i] = fsrc[i];
        }
#pragma unroll 4
        for (int kk = 0; kk < 32; kk++) {
            u64 w[4];
#pragma unroll
            for (int j = 0; j < 4; j++)
                w[j] = *(const u64*)(sW + kk * 128 + 8 * cg + 2 * j);
            u64 x[8];
#pragma unroll
            for (int i = 0; i < 8; i++)
                x[i] = sF2[(rg * 8 + i) * 33 + kk];
#pragma unroll
            for (int i = 0; i < 8; i++)
#pragma unroll
                for (int j = 0; j < 4; j++)
                    acc[i][j] = fma2(x[i], w[j], acc[i][j]);
        }
    }

    float2 b2[4];
#pragma unroll
    for (int j = 0; j < 4; j++) b2[j] = ((const float2*)bias)[cg * 4 + j];
#pragma unroll
    for (int i = 0; i < 8; i++) {
        int row = row0 + rg * 8 + i;
        if (row < N) {
#pragma unroll
            for (int j = 0; j < 4; j++) {
                float2 a = unpack2(acc[i][j]);
                a.x += b2[j].x; a.y += b2[j].y;
                ((float2*)E)[(size_t)row * 64 + cg * 4 + j] = a;
            }
        }
    }
}

// ---------------- 2) XW precompute (512 thr, cp.async double-buffered W) ------
// 64 gathered rows/block; thread tile = 8 rows x 3 col-pairs (cg + j*64).
// W streamed as four 32-k tiles, double buffered via cp.async.
__global__ __launch_bounds__(512) void xw_kernel(
    const float* __restrict__ gruW, const float* __restrict__ gruB,
    const int* __restrict__ nbr_d, const int* __restrict__ nbr_g,
    const int* __restrict__ nbr_c)
{
    extern __shared__ float sm[];
    float* sW  = sm;                       // 2 x (32*384) floats = 96KB
    u64*   sX2 = (u64*)(sm + 24576);       // 64 rows x 128 = 64KB
    int*   sId = (int*)(sX2 + 64 * 128);   // 64

    int tid = threadIdx.x;
    int lt = blockIdx.y;
    int t3 = lt % 3;
    const int* nbr = (t3 == 0) ? nbr_d : (t3 == 1) ? nbr_g : nbr_c;
    const float* Etab = (t3 == 0) ? g_E_drug : (t3 == 1) ? g_E_gene : g_E_cell;
    int grow0 = blockIdx.x * 64;

    const float* Wbase = gruW + (size_t)lt * 49152;

    if (tid < 64) sId[tid] = nbr[grow0 + tid];

    // kick off W tile 0 DMA
    {
        unsigned d = smem_addr(sW);
        const float4* src = (const float4*)Wbase;
#pragma unroll
        for (int i = 0; i < 6; i++)
            cp16(d + (tid + i * 512) * 16, src + tid + i * 512);
        asm volatile("cp.async.commit_group;");
    }
    __syncthreads();   // sId visible

    // stage gathered X (duplicated splats), all 128 k — overlaps tile-0 DMA
    {
        int r = tid >> 3;
        int kq = (tid & 7) * 16;
        int id = sId[r];
        const float4* src = (id >= 0) ? (const float4*)(Etab + (size_t)id * 128 + kq) : 0;
#pragma unroll
        for (int i = 0; i < 4; i++) {
            float4 f = (id >= 0) ? src[i] : make_float4(0.f, 0.f, 0.f, 0.f);
            int base = r * 128 + kq + i * 4;
            sX2[base + 0] = splat2(f.x);
            sX2[base + 1] = splat2(f.y);
            sX2[base + 2] = splat2(f.z);
            sX2[base + 3] = splat2(f.w);
        }
    }

    int cg = tid & 63;       // pairs cg + j*64, j in [0,3)
    int rg = tid >> 6;       // rows rg*8 .. rg*8+7

    u64 acc[8][3];
#pragma unroll
    for (int i = 0; i < 8; i++)
#pragma unroll
        for (int j = 0; j < 3; j++) acc[i][j] = 0ull;

#pragma unroll
    for (int t = 0; t < 4; t++) {
        if (t < 3) {   // prefetch next W tile into alternate buffer
            unsigned d = smem_addr(sW + ((t + 1) & 1) * 12288);
            const float4* src = (const float4*)(Wbase + (t + 1) * 12288);
#pragma unroll
            for (int i = 0; i < 6; i++)
                cp16(d + (tid + i * 512) * 16, src + tid + i * 512);
            asm volatile("cp.async.commit_group;");
            asm volatile("cp.async.wait_group 1;");
        } else {
            asm volatile("cp.async.wait_group 0;");
        }
        __syncthreads();   // tile t visible to all; X staged (t=0)

        const float* wt = sW + (t & 1) * 12288;
#pragma unroll 4
        for (int kk = 0; kk < 32; kk++) {
            u64 x[8];
#pragma unroll
            for (int i = 0; i < 8; i++)
                x[i] = sX2[(rg * 8 + i) * 128 + t * 32 + kk];
            u64 w[3];
#pragma unroll
            for (int j = 0; j < 3; j++)
                w[j] = *(const u64*)(wt + kk * 384 + 2 * (cg + j * 64));
#pragma unroll
            for (int i = 0; i < 8; i++)
#pragma unroll
                for (int j = 0; j < 3; j++)
                    acc[i][j] = fma2(x[i], w[j], acc[i][j]);
        }
        __syncthreads();   // done reading buffer before next DMA overwrites it
    }

    float2 b2[3];
#pragma unroll
    for (int j = 0; j < 3; j++) b2[j] = ((const float2*)(gruB + lt * 384))[cg + j * 64];
#pragma unroll
    for (int i = 0; i < 8; i++) {
        int grow = grow0 + rg * 8 + i;
#pragma unroll
        for (int j = 0; j < 3; j++) {
            float2 a = unpack2(acc[i][j]);
            a.x += b2[j].x; a.y += b2[j].y;
            ((float2*)g_XW)[((size_t)lt * 40960 + grow) * 192 + cg + j * 64] = a;
        }
    }
}

// ---------------- 3) GRU recurrence + masked mean (512 thr) ----------------
// 32 batch rows/block; 64 dim-pairs x 8 row-parts (4 rows each).
// U (192KB) + duplicated H (32KB) in smem; XW gate inputs prefetched to regs.
__global__ __launch_bounds__(512) void gru_kernel(
    const float* __restrict__ gruU,
    const int* __restrict__ nbr_d, const int* __restrict__ nbr_g,
    const int* __restrict__ nbr_c)
{
    extern __shared__ float sm[];
    float*  sU  = sm;                          // 128*384
    float2* sH2 = (float2*)(sm + 49152);       // [32][128] duplicated splats
    float*  sM  = (float*)(sH2 + 32 * 128);    // [32][10]
    float*  sCnt = sM + 320;                   // [32]

    int tid = threadIdx.x;
    int lt = blockIdx.y;
    int t3 = lt % 3;
    const int* nbr = (t3 == 0) ? nbr_d : (t3 == 1) ? nbr_g : nbr_c;
    int b0 = blockIdx.x * 32;

    {
        const float4* src = (const float4*)(gruU + (size_t)lt * 49152);
        float4* dst = (float4*)sU;
#pragma unroll
        for (int i = 0; i < 24; i++) dst[tid + i * 512] = src[tid + i * 512];
    }
    if (tid < 320) {
        int rr = tid / 10, s = tid % 10;
        sM[tid] = (nbr[(size_t)(b0 + rr) * 10 + s] >= 0) ? 1.f : 0.f;
    }
    for (int i = tid; i < 4096; i += 512) sH2[i] = make_float2(0.f, 0.f);
    __syncthreads();
    if (tid < 32) {
        float cnt = 0.f;
        for (int s = 0; s < 10; s++) cnt += sM[tid * 10 + s];
        sCnt[tid] = fmaxf(cnt, 1.f);
    }
    __syncthreads();

    int d2 = tid & 63, rpart = tid >> 6;   // 4 rows per thread
    float2 msum[4];
#pragma unroll
    for (int i = 0; i < 4; i++) msum[i] = make_float2(0.f, 0.f);

    for (int s = 0; s < 10; s++) {
        // prefetch this step's gate inputs (global) — hidden under the GEMM
        float2 pxz[4], pxr[4], pxn[4];
#pragma unroll
        for (int i = 0; i < 4; i++) {
            int bg = b0 + rpart * 4 + i;
            const float* xwb = g_XW + ((size_t)lt * 40960 + (size_t)bg * 10 + s) * 384;
            pxz[i] = *(const float2*)(xwb + 2 * d2);
            pxr[i] = *(const float2*)(xwb + 128 + 2 * d2);
            pxn[i] = *(const float2*)(xwb + 256 + 2 * d2);
        }

        u64 az[4], ar[4], an[4];
#pragma unroll
        for (int i = 0; i < 4; i++) { az[i] = 0ull; ar[i] = 0ull; an[i] = 0ull; }

#pragma unroll 4
        for (int k = 0; k < 128; k++) {
            u64 uz = *(const u64*)(sU + k * 384 + 2 * d2);
            u64 ur = *(const u64*)(sU + k * 384 + 128 + 2 * d2);
            u64 un = *(const u64*)(sU + k * 384 + 256 + 2 * d2);
#pragma unroll
            for (int i = 0; i < 4; i++) {
                u64 hh = *(const u64*)(sH2 + (rpart * 4 + i) * 128 + k);
                az[i] = fma2(hh, uz, az[i]);
                ar[i] = fma2(hh, ur, ar[i]);
                an[i] = fma2(hh, un, an[i]);
            }
        }
        __syncthreads();   // all reads of H done before updates
#pragma unroll
        for (int i = 0; i < 4; i++) {
            int rl = rpart * 4 + i;
            float2 hz = unpack2(az[i]), hr = unpack2(ar[i]), hn = unpack2(an[i]);
            float hox = sH2[rl * 128 + 2 * d2].x;
            float hoy = sH2[rl * 128 + 2 * d2 + 1].x;
            float zx = sigmf(pxz[i].x + hz.x), zy = sigmf(pxz[i].y + hz.y);
            float rx = sigmf(pxr[i].x + hr.x), ry = sigmf(pxr[i].y + hr.y);
            float nx = tanh_fast(pxn[i].x + rx * hn.x);
            float ny = tanh_fast(pxn[i].y + ry * hn.y);
            float hx = (1.f - zx) * nx + zx * hox;
            float hy = (1.f - zy) * ny + zy * hoy;
            sH2[rl * 128 + 2 * d2]     = make_float2(hx, hx);
            sH2[rl * 128 + 2 * d2 + 1] = make_float2(hy, hy);
            float m = sM[rl * 10 + s];
            msum[i].x += m * hx;
            msum[i].y += m * hy;
        }
        __syncthreads();
    }
#pragma unroll
    for (int i = 0; i < 4; i++) {
        int rl = rpart * 4 + i;
        int bg = b0 + rl;
        float invc = 1.f / sCnt[rl];
        ((float2*)g_S)[((size_t)lt * BB + bg) * 64 + d2] =
            make_float2(msum[i].x * invc, msum[i].y * invc);
    }
}

// ---------------- 4) attention combine (2 layers) ----------------
__device__ __forceinline__ float blkred(float v, float* red) {
    int d = threadIdx.x;
    red[d] = v;
    __syncthreads();
#pragma unroll
    for (int st = 64; st > 0; st >>= 1) {
        if (d < st) red[d] += red[d + st];
        __syncthreads();
    }
    float r = red[0];
    __syncthreads();
    return r;
}

__global__ __launch_bounds__(128) void final_kernel(
    const float* __restrict__ att, const int* __restrict__ ids,
    float* __restrict__ out)
{
    __shared__ float red[128];
    __shared__ float sC[3][128];
    int b = blockIdx.x, d = threadIdx.x;
    float h = g_E_drug[(size_t)ids[b] * 128 + d];
#pragma unroll
    for (int l = 0; l < 2; l++) {
        for (int t = 0; t < 3; t++)
            sC[t][d] = g_S[((size_t)(l * 3 + t) * BB + b) * 128 + d];
        __syncthreads();
        float a1 = att[l * 256 + d], a2 = att[l * 256 + 128 + d];
        float dh1 = blkred(h * a1, red);
        float dh2 = blkred(h * a2, red);
        float e0 = dh1 + dh2;
        float e1 = dh1 + blkred(sC[0][d] * a2, red);
        float e2 = dh1 + blkred(sC[1][d] * a2, red);
        float e3 = dh1 + blkred(sC[2][d] * a2, red);
        e0 = e0 > 0.f ? e0 : 0.01f * e0;
        e1 = e1 > 0.f ? e1 : 0.01f * e1;
        e2 = e2 > 0.f ? e2 : 0.01f * e2;
        e3 = e3 > 0.f ? e3 : 0.01f * e3;
        float mx = fmaxf(fmaxf(e0, e1), fmaxf(e2, e3));
        float w0 = __expf(e0 - mx), w1 = __expf(e1 - mx);
        float w2 = __expf(e2 - mx), w3 = __expf(e3 - mx);
        float inv = __fdividef(1.f, w0 + w1 + w2 + w3);
        h = (w0 * h + w1 * sC[0][d] + w2 * sC[1][d] + w3 * sC[2][d]) * inv;
        __syncthreads();
    }
    out[(size_t)b * 128 + d] = h;
}

// ---------------- launch ----------------
extern "C" void kernel_launch(void* const* d_in, const int* in_sizes, int n_in,
                              void* d_out, int out_size)
{
    const float* drug = (const float*)d_in[0];
    const float* gene = (const float*)d_in[1];
    const float* cell = (const float*)d_in[2];
    const float* Wd = (const float*)d_in[3];
    const float* bd = (const float*)d_in[4];
    const float* Wg = (const float*)d_in[5];
    const float* bg = (const float*)d_in[6];
    const float* Wc = (const float*)d_in[7];
    const float* bc = (const float*)d_in[8];
    const float* gW = (const float*)d_in[9];
    const float* gU = (const float*)d_in[10];
    const float* gb = (const float*)d_in[11];
    const float* att = (const float*)d_in[12];
    const int* ids = (const int*)d_in[13];
    const int* nd = (const int*)d_in[14];
    const int* ng = (const int*)d_in[15];
    const int* nc = (const int*)d_in[16];
    float* out = (float*)d_out;

    const int XW_SMEM  = 2 * 32 * 384 * 4 + 64 * 128 * 8 + 64 * 4;        // 164_352
    const int GRU_SMEM = 128 * 384 * 4 + 32 * 128 * 8 + 320 * 4 + 32 * 4; // 230784
    cudaFuncSetAttribute(xw_kernel, cudaFuncAttributeMaxDynamicSharedMemorySize, XW_SMEM);
    cudaFuncSetAttribute(gru_kernel, cudaFuncAttributeMaxDynamicSharedMemorySize, GRU_SMEM);

    // 1) project tables once
    proj_kernel<<<(ND + 127) / 128, 256>>>(drug, Wd, bd, 0, ND, 2048);
    proj_kernel<<<(NG + 127) / 128, 256>>>(gene, Wg, bg, 1, NG, 1024);
    proj_kernel<<<(NC + 127) / 128, 256>>>(cell, Wc, bc, 2, NC, 512);

    // 2) XW = gathered X @ W + b for all 6 (layer,type)
    xw_kernel<<<dim3(40960 / 64, 6), 512, XW_SMEM>>>(gW, gb, nd, ng, nc);

    // 3) GRU recurrence + masked mean for all 6 (layer,type)
    gru_kernel<<<dim3(BB / 32, 6), 512, GRU_SMEM>>>(gU, nd, ng, nc);

    // 4) attention combine (both layers) + output
    final_kernel<<<BB, 128>>>(att, ids, out);
}